// round 2
// baseline (speedup 1.0000x reference)
#include <cuda_runtime.h>

// Problem constants (fixed by the dataset)
#define NB   64          // batch
#define T1   4097        // maxT+1
#define MAXT 4096
#define HB   16          // hidden states
#define NA   18          // actions
#define CL   64          // chunk length (steps per chunk)
#define NC   64          // chunks per batch (covers steps i = 1..4095)

// Scratch: per (batch, chunk) transfer matrix (g_mats[b][ch][k][c] = M[k][c],
// column c carries log-scale g_lam) — true matrix = M[:,c] * exp(lam[c]).
__device__ float g_mats[NB * NC * HB * HB];
__device__ float g_lam[NB * NC * HB];

// Prefetch bank: 8 steps of (stop.xy, start, action_logp) per lane.
struct PFB { float2 s[8]; float t[8]; float a[8]; };

__device__ __forceinline__ void load_group(
    int g0, int nact, unsigned idx16_0,
    const float2* __restrict__ stop2, const float* __restrict__ startl,
    const float* __restrict__ alogp, const int* __restrict__ sa,
    PFB& B)
{
#pragma unroll
    for (int u = 0; u < 8; ++u) {
        int t = g0 + u;
        if (t < nact) {
            unsigned idx = idx16_0 + (unsigned)t * 16u;
            B.s[u] = __ldg(stop2 + idx);                       // (beta, omb)
            B.t[u] = __ldg(startl + idx);                      // start
            B.a[u] = __ldg(alogp + idx * 18u + (unsigned)sa[t]); // action logp
        } else {
            B.s[u] = make_float2(0.f, 0.f); B.t[u] = 0.f; B.a[u] = 0.f;
        }
    }
}

// Per step i (exact linear map, no per-step normalization needed):
//   s       = sum_j exp(beta_j) * p[j]
//   p[k]   <- exp(al_k+start_k)*s + exp(al_k+omb_k)*p[k]
// Every 2 steps: p /= s, lam += log(s)  (pure conditioning; p*e^lam invariant).
__device__ __forceinline__ void consume_group(
    int g0, int nsteps, int nact, int c, float* __restrict__ vb2,
    PFB& B, float (&p)[HB], float& lam)
{
#pragma unroll
    for (int u = 0; u < 8; ++u) {
        int t = g0 + u;
        if (t >= nsteps) return;   // nsteps is warp-uniform
        float eb   = __expf(B.s[u].x);
        float easv = __expf(B.a[u] + B.t[u]);
        float eaov = __expf(B.a[u] + B.s[u].y);
        float* vb = vb2 + (u & 1) * 48;
        vb[c]      = eb;
        vb[16 + c] = easv;
        vb[32 + c] = eaov;
        __syncwarp();
        const float4* EB = (const float4*)vb;
        float4 e0 = EB[0], e1 = EB[1], e2 = EB[2], e3 = EB[3];
        float t0 = fmaf(e0.x, p[0],  e0.y * p[1])  + fmaf(e0.z, p[2],  e0.w * p[3]);
        float t1 = fmaf(e1.x, p[4],  e1.y * p[5])  + fmaf(e1.z, p[6],  e1.w * p[7]);
        float t2 = fmaf(e2.x, p[8],  e2.y * p[9])  + fmaf(e2.z, p[10], e2.w * p[11]);
        float t3 = fmaf(e3.x, p[12], e3.y * p[13]) + fmaf(e3.z, p[14], e3.w * p[15]);
        float s = (t0 + t1) + (t2 + t3);
        if (t < nact) {            // uniform within each half-warp
            const float4* EA = (const float4*)(vb + 16);
            const float4* EO = (const float4*)(vb + 32);
            float4 a0 = EA[0], a1 = EA[1], a2 = EA[2], a3 = EA[3];
            float4 o0 = EO[0], o1 = EO[1], o2 = EO[2], o3 = EO[3];
            p[0]  = fmaf(o0.x, p[0],  a0.x * s);
            p[1]  = fmaf(o0.y, p[1],  a0.y * s);
            p[2]  = fmaf(o0.z, p[2],  a0.z * s);
            p[3]  = fmaf(o0.w, p[3],  a0.w * s);
            p[4]  = fmaf(o1.x, p[4],  a1.x * s);
            p[5]  = fmaf(o1.y, p[5],  a1.y * s);
            p[6]  = fmaf(o1.z, p[6],  a1.z * s);
            p[7]  = fmaf(o1.w, p[7],  a1.w * s);
            p[8]  = fmaf(o2.x, p[8],  a2.x * s);
            p[9]  = fmaf(o2.y, p[9],  a2.y * s);
            p[10] = fmaf(o2.z, p[10], a2.z * s);
            p[11] = fmaf(o2.w, p[11], a2.w * s);
            p[12] = fmaf(o3.x, p[12], a3.x * s);
            p[13] = fmaf(o3.y, p[13], a3.y * s);
            p[14] = fmaf(o3.z, p[14], a3.z * s);
            p[15] = fmaf(o3.w, p[15], a3.w * s);
            if (t & 1) {
                float r = __fdividef(1.0f, s);
                lam += __logf(s);
#pragma unroll
                for (int k = 0; k < HB; ++k) p[k] *= r;
            }
        }
    }
}

// One warp handles TWO chunks: lanes 0-15 = chunk 2*pr, lanes 16-31 = chunk 2*pr+1.
__global__ __launch_bounds__(128) void hmm_chunk_kernel(
    const float* __restrict__ alogp,
    const float* __restrict__ stopl,
    const float* __restrict__ startl,
    const int* __restrict__ actions,
    const int* __restrict__ lengths,
    float* __restrict__ out)
{
    if (blockIdx.x == 0 && threadIdx.x == 0) *out = 0.0f;

    const int wib  = threadIdx.x >> 5;
    const int lane = threadIdx.x & 31;
    const int gw   = blockIdx.x * 4 + wib;     // 0..2047
    const int b    = gw >> 5;                  // 64 batches
    const int pr   = gw & 31;                  // 32 chunk-pairs
    const int sub  = lane >> 4;
    const int c    = lane & 15;
    const int ch   = pr * 2 + sub;
    const int i0   = 1 + ch * CL;

    __shared__ int s_act[4][2 * CL];
    __shared__ __align__(16) float s_vec[4][2][2][3 * HB];

    const int len = lengths[b];

    // my chunk's active steps
    int cnt  = min(CL, MAXT - i0);
    int nact = max(0, min(len - i0, cnt));
    // warp-uniform step count (max over both subs)
    const int i0p  = 1 + pr * 2 * CL;
    int n0 = max(0, min(len - i0p, min(CL, MAXT - i0p)));
    int n1 = max(0, min(len - (i0p + CL), min(CL, MAXT - (i0p + CL))));
    int nsteps = max(n0, n1);

    // actions for the whole pair region (contiguous)
    int totA = min(2 * CL, MAXT - i0p);
    for (int idx = lane; idx < totA; idx += 32)
        s_act[wib][idx] = actions[(size_t)b * MAXT + i0p + idx];
    __syncwarp();

    float p[HB];
#pragma unroll
    for (int k = 0; k < HB; ++k) p[k] = (k == c) ? 1.0f : 0.0f;
    float lam = 0.0f;

    if (nsteps > 0) {
        const unsigned idx16_0 = ((unsigned)b * T1 + (unsigned)i0) * 16u + (unsigned)c;
        const float2* stop2 = (const float2*)stopl;
        const int* sa = &s_act[wib][sub * CL];
        float* vb2 = &s_vec[wib][sub][0][0];

        PFB B0, B1;
        load_group(0, nact, idx16_0, stop2, startl, alogp, sa, B0);
        for (int g0 = 0; g0 < nsteps; g0 += 16) {
            load_group(g0 + 8, nact, idx16_0, stop2, startl, alogp, sa, B1);
            consume_group(g0, nsteps, nact, c, vb2, B0, p, lam);
            if (g0 + 8 < nsteps) {
                load_group(g0 + 16, nact, idx16_0, stop2, startl, alogp, sa, B0);
                consume_group(g0 + 8, nsteps, nact, c, vb2, B1, p, lam);
            }
        }
    }

    // store my chunk's matrix column (row-major: [k][c] for coalesced combine reads)
    {
        size_t mb = (size_t)(b * NC + ch) * (HB * HB);
#pragma unroll
        for (int k = 0; k < HB; ++k)
            g_mats[mb + (size_t)k * HB + c] = p[k];
        g_lam[(size_t)(b * NC + ch) * HB + c] = lam;
    }
}

// ---------------------------------------------------------------------------
// Combine kernel: one warp per batch, f kept in log domain across chunks.
//   f_new[k] = m + log( sum_c M[k][c] * exp(f[c] + lam[c] - m) )
// ---------------------------------------------------------------------------
__global__ __launch_bounds__(32) void hmm_combine_kernel(
    const float* __restrict__ alogp,
    const float* __restrict__ stopl,
    const float* __restrict__ startl,
    const int* __restrict__ actions,
    const int* __restrict__ lengths,
    float* __restrict__ out)
{
    const int b = blockIdx.x;
    const int lane = threadIdx.x;
    const int c = lane & 15;
    __shared__ __align__(16) float wbuf[2][HB];

    const int len = lengths[b];
    const int a0i = actions[(size_t)b * MAXT];
    const size_t rb = (size_t)b * T1;

    float f = startl[rb * 16 + c] + alogp[(rb * 16 + (size_t)c) * 18 + a0i];

    // preload chunk 0 (lane c holds row c of M: M[c][j], j=0..15)
    float4 r0, r1, r2, r3; float lamv;
    {
        const float4* mp = (const float4*)(g_mats + ((size_t)(b * NC) * HB + c) * HB);
        r0 = mp[0]; r1 = mp[1]; r2 = mp[2]; r3 = mp[3];
        lamv = g_lam[(size_t)(b * NC) * HB + c];
    }

    for (int ch = 0; ch < NC; ++ch) {
        float4 n0 = r0, n1 = r1, n2 = r2, n3 = r3; float nlam = lamv;
        if (ch + 1 < NC) {
            const float4* mp = (const float4*)(g_mats + ((size_t)(b * NC + ch + 1) * HB + c) * HB);
            n0 = mp[0]; n1 = mp[1]; n2 = mp[2]; n3 = mp[3];
            nlam = g_lam[(size_t)(b * NC + ch + 1) * HB + c];
        }
        float t = f + lamv;
        float m = t;
        m = fmaxf(m, __shfl_xor_sync(0xffffffffu, m, 1));
        m = fmaxf(m, __shfl_xor_sync(0xffffffffu, m, 2));
        m = fmaxf(m, __shfl_xor_sync(0xffffffffu, m, 4));
        m = fmaxf(m, __shfl_xor_sync(0xffffffffu, m, 8));
        float wv = __expf(t - m);
        if (lane < 16) wbuf[ch & 1][c] = wv;
        __syncwarp();
        const float4* W = (const float4*)wbuf[ch & 1];
        float4 w0 = W[0], w1 = W[1], w2 = W[2], w3 = W[3];
        float d0 = r0.x * w0.x + r0.y * w0.y + r0.z * w0.z + r0.w * w0.w;
        float d1 = r1.x * w1.x + r1.y * w1.y + r1.z * w1.z + r1.w * w1.w;
        float d2 = r2.x * w2.x + r2.y * w2.y + r2.z * w2.z + r2.w * w2.w;
        float d3 = r3.x * w3.x + r3.y * w3.y + r3.z * w3.z + r3.w * w3.w;
        float dot = (d0 + d1) + (d2 + d3);
        f = m + __logf(dot);
        r0 = n0; r1 = n1; r2 = n2; r3 = n3; lamv = nlam;
    }

    // final: -logsumexp_k( f[k] + stop_logps[b, len, k, STOP] )
    float stT = stopl[((rb + (size_t)len) * 16 + (size_t)c) * 2];
    float t = f + stT;
    float m = t;
    m = fmaxf(m, __shfl_xor_sync(0xffffffffu, m, 1));
    m = fmaxf(m, __shfl_xor_sync(0xffffffffu, m, 2));
    m = fmaxf(m, __shfl_xor_sync(0xffffffffu, m, 4));
    m = fmaxf(m, __shfl_xor_sync(0xffffffffu, m, 8));
    float wv = __expf(t - m);
    float sum = wv;
    sum += __shfl_xor_sync(0xffffffffu, sum, 1);
    sum += __shfl_xor_sync(0xffffffffu, sum, 2);
    sum += __shfl_xor_sync(0xffffffffu, sum, 4);
    sum += __shfl_xor_sync(0xffffffffu, sum, 8);
    sum += __shfl_xor_sync(0xffffffffu, sum, 16);  // halves duplicated => 2x
    if (lane == 0) atomicAdd(out, -(m + __logf(0.5f * sum)));
}

extern "C" void kernel_launch(void* const* d_in, const int* in_sizes, int n_in,
                              void* d_out, int out_size)
{
    const float* alogp   = (const float*)d_in[0];
    const float* stopl   = (const float*)d_in[1];
    const float* startl  = (const float*)d_in[2];
    const int*   actions = (const int*)d_in[3];
    const int*   lengths = (const int*)d_in[4];
    float* out = (float*)d_out;

    hmm_chunk_kernel<<<(NB * NC / 2) / 4, 128>>>(alogp, stopl, startl, actions, lengths, out);
    hmm_combine_kernel<<<NB, 32>>>(alogp, stopl, startl, actions, lengths, out);
}

// round 3
// speedup vs baseline: 1.1168x; 1.1168x over previous
#include <cuda_runtime.h>

// Problem constants (fixed by the dataset)
#define NB   64          // batch
#define T1   4097        // maxT+1
#define MAXT 4096
#define HB   16          // hidden states
#define NA   18          // actions
#define CL   32          // chunk length (steps per chunk)
#define NC   128         // chunks per batch (covers steps i = 1..4095)

// Scratch: per (batch, chunk) transfer matrix (g_mats[b][ch][k][c] = M[k][c],
// column c carries log-scale g_lam) — true matrix = M[:,c] * exp(lam[c]).
__device__ float g_mats[NB * NC * HB * HB];   // 8 MB
__device__ float g_lam[NB * NC * HB];

// Prefetch bank: 8 steps of (stop.xy, start, action_logp) per lane.
struct PFB { float2 s[8]; float t[8]; float a[8]; };

__device__ __forceinline__ void load_group(
    int g0, int nact, unsigned idx16_0,
    const float2* __restrict__ stop2, const float* __restrict__ startl,
    const float* __restrict__ alogp, const int* __restrict__ sa,
    PFB& B)
{
#pragma unroll
    for (int u = 0; u < 8; ++u) {
        int t = g0 + u;
        if (t < nact) {
            unsigned idx = idx16_0 + (unsigned)t * 16u;
            B.s[u] = __ldg(stop2 + idx);                         // (beta, omb)
            B.t[u] = __ldg(startl + idx);                        // start
            B.a[u] = __ldg(alogp + idx * 18u + (unsigned)sa[t]); // action logp
        } else {
            B.s[u] = make_float2(0.f, 0.f); B.t[u] = 0.f; B.a[u] = 0.f;
        }
    }
}

// Per step i (exact linear map, no per-step normalization needed):
//   s     = sum_j exp(beta_j) * p[j]
//   p[k] <- exp(al_k+start_k)*s + exp(al_k+omb_k)*p[k]
// Every 2 steps: p /= s, lam += log(s)  (pure conditioning; p*e^lam invariant).
__device__ __forceinline__ void consume_group(
    int g0, int nsteps, int nact, int c, float* __restrict__ vb2,
    PFB& B, float (&p)[HB], float& lam)
{
#pragma unroll
    for (int u = 0; u < 8; ++u) {
        int t = g0 + u;
        if (t >= nsteps) return;   // nsteps is warp-uniform
        float eb   = __expf(B.s[u].x);
        float easv = __expf(B.a[u] + B.t[u]);
        float eaov = __expf(B.a[u] + B.s[u].y);
        float* vb = vb2 + (u & 1) * 48;
        vb[c]      = eb;
        vb[16 + c] = easv;
        vb[32 + c] = eaov;
        __syncwarp();
        const float4* EB = (const float4*)vb;
        float4 e0 = EB[0], e1 = EB[1], e2 = EB[2], e3 = EB[3];
        float t0 = fmaf(e0.x, p[0],  e0.y * p[1])  + fmaf(e0.z, p[2],  e0.w * p[3]);
        float t1 = fmaf(e1.x, p[4],  e1.y * p[5])  + fmaf(e1.z, p[6],  e1.w * p[7]);
        float t2 = fmaf(e2.x, p[8],  e2.y * p[9])  + fmaf(e2.z, p[10], e2.w * p[11]);
        float t3 = fmaf(e3.x, p[12], e3.y * p[13]) + fmaf(e3.z, p[14], e3.w * p[15]);
        float s = (t0 + t1) + (t2 + t3);
        if (t < nact) {            // uniform within each half-warp
            const float4* EA = (const float4*)(vb + 16);
            const float4* EO = (const float4*)(vb + 32);
            float4 a0 = EA[0], a1 = EA[1], a2 = EA[2], a3 = EA[3];
            float4 o0 = EO[0], o1 = EO[1], o2 = EO[2], o3 = EO[3];
            p[0]  = fmaf(o0.x, p[0],  a0.x * s);
            p[1]  = fmaf(o0.y, p[1],  a0.y * s);
            p[2]  = fmaf(o0.z, p[2],  a0.z * s);
            p[3]  = fmaf(o0.w, p[3],  a0.w * s);
            p[4]  = fmaf(o1.x, p[4],  a1.x * s);
            p[5]  = fmaf(o1.y, p[5],  a1.y * s);
            p[6]  = fmaf(o1.z, p[6],  a1.z * s);
            p[7]  = fmaf(o1.w, p[7],  a1.w * s);
            p[8]  = fmaf(o2.x, p[8],  a2.x * s);
            p[9]  = fmaf(o2.y, p[9],  a2.y * s);
            p[10] = fmaf(o2.z, p[10], a2.z * s);
            p[11] = fmaf(o2.w, p[11], a2.w * s);
            p[12] = fmaf(o3.x, p[12], a3.x * s);
            p[13] = fmaf(o3.y, p[13], a3.y * s);
            p[14] = fmaf(o3.z, p[14], a3.z * s);
            p[15] = fmaf(o3.w, p[15], a3.w * s);
            if (t & 1) {
                float r = __fdividef(1.0f, s);
                lam += __logf(s);
#pragma unroll
                for (int k = 0; k < HB; ++k) p[k] *= r;
            }
        }
    }
}

// One warp handles TWO chunks: lanes 0-15 = chunk 2*pr, lanes 16-31 = chunk 2*pr+1.
__global__ __launch_bounds__(128) void hmm_chunk_kernel(
    const float* __restrict__ alogp,
    const float* __restrict__ stopl,
    const float* __restrict__ startl,
    const int* __restrict__ actions,
    const int* __restrict__ lengths,
    float* __restrict__ out)
{
    if (blockIdx.x == 0 && threadIdx.x == 0) *out = 0.0f;

    const int wib  = threadIdx.x >> 5;
    const int lane = threadIdx.x & 31;
    const int gw   = blockIdx.x * 4 + wib;     // 0..4095
    const int b    = gw >> 6;                  // 64 batches
    const int pr   = gw & 63;                  // 64 chunk-pairs
    const int sub  = lane >> 4;
    const int c    = lane & 15;
    const int ch   = pr * 2 + sub;
    const int i0   = 1 + ch * CL;

    __shared__ int s_act[4][2 * CL];
    __shared__ __align__(16) float s_vec[4][2][2][3 * HB];

    const int len = lengths[b];

    // my chunk's active steps
    int cnt  = min(CL, MAXT - i0);
    int nact = max(0, min(len - i0, cnt));
    // warp-uniform step count (max over both subs)
    const int i0p  = 1 + pr * 2 * CL;
    int n0 = max(0, min(len - i0p, min(CL, MAXT - i0p)));
    int n1 = max(0, min(len - (i0p + CL), min(CL, MAXT - (i0p + CL))));
    int nsteps = max(n0, n1);

    // actions for the whole pair region (contiguous)
    int totA = min(2 * CL, MAXT - i0p);
    for (int idx = lane; idx < totA; idx += 32)
        s_act[wib][idx] = actions[(size_t)b * MAXT + i0p + idx];
    __syncwarp();

    float p[HB];
#pragma unroll
    for (int k = 0; k < HB; ++k) p[k] = (k == c) ? 1.0f : 0.0f;
    float lam = 0.0f;

    if (nsteps > 0) {
        const unsigned idx16_0 = ((unsigned)b * T1 + (unsigned)i0) * 16u + (unsigned)c;
        const float2* stop2 = (const float2*)stopl;
        const int* sa = &s_act[wib][sub * CL];
        float* vb2 = &s_vec[wib][sub][0][0];

        PFB B0, B1;
        load_group(0, nact, idx16_0, stop2, startl, alogp, sa, B0);
        for (int g0 = 0; g0 < nsteps; g0 += 16) {
            load_group(g0 + 8, nact, idx16_0, stop2, startl, alogp, sa, B1);
            consume_group(g0, nsteps, nact, c, vb2, B0, p, lam);
            if (g0 + 8 < nsteps) {
                load_group(g0 + 16, nact, idx16_0, stop2, startl, alogp, sa, B0);
                consume_group(g0 + 8, nsteps, nact, c, vb2, B1, p, lam);
            }
        }
    }

    // store my chunk's matrix column (row-major: [k][c])
    {
        size_t mb = (size_t)(b * NC + ch) * (HB * HB);
#pragma unroll
        for (int k = 0; k < HB; ++k)
            g_mats[mb + (size_t)k * HB + c] = p[k];
        g_lam[(size_t)(b * NC + ch) * HB + c] = lam;
    }
}

// ---------------------------------------------------------------------------
// Tree combine: one block (16 warps) per batch. Chunk matrices compose
// associatively: true M = Mhat * diag(e^lam).
//   C_true = A_true * P_true, C[k][c] = sum_j A[k][j] e^{lamA[j]-mA} P[j][c],
//   lamC[c] = lamP[c] + mA + log(max_k C[k][c]); renormalize columns by max.
// ---------------------------------------------------------------------------
__device__ __forceinline__ void mat_product(
    const float* __restrict__ srcM, const float* __restrict__ srcLam,
    float* __restrict__ dstM, float* __restrict__ dstLam,
    int p, int lane, float* __restrict__ sea /* per-warp 16-float scratch */)
{
    const int c = lane & 15;
    // P = src mat (2p) [earlier in time], A = src mat (2p+1) [later]
    float pc[16];
    const float* Pm = srcM + (size_t)(2 * p) * 256;
#pragma unroll
    for (int j = 0; j < 16; ++j) pc[j] = Pm[j * 16 + c];
    float lamP = srcLam[(2 * p) * 16 + c];
    float lamA = srcLam[(2 * p + 1) * 16 + c];
    float mA = lamA;
    mA = fmaxf(mA, __shfl_xor_sync(0xffffffffu, mA, 1));
    mA = fmaxf(mA, __shfl_xor_sync(0xffffffffu, mA, 2));
    mA = fmaxf(mA, __shfl_xor_sync(0xffffffffu, mA, 4));
    mA = fmaxf(mA, __shfl_xor_sync(0xffffffffu, mA, 8));
    if (lane < 16) sea[c] = __expf(lamA - mA);
    __syncwarp();
    float w[16];
#pragma unroll
    for (int j = 0; j < 16; ++j) w[j] = sea[j] * pc[j];
    __syncwarp();
    const float4* Am = (const float4*)(srcM + (size_t)(2 * p + 1) * 256);
    float Cv[16];
#pragma unroll
    for (int k = 0; k < 16; ++k) {
        float4 a0 = Am[k * 4 + 0], a1 = Am[k * 4 + 1];
        float4 a2 = Am[k * 4 + 2], a3 = Am[k * 4 + 3];
        float d0 = fmaf(a0.x, w[0],  a0.y * w[1])  + fmaf(a0.z, w[2],  a0.w * w[3]);
        float d1 = fmaf(a1.x, w[4],  a1.y * w[5])  + fmaf(a1.z, w[6],  a1.w * w[7]);
        float d2 = fmaf(a2.x, w[8],  a2.y * w[9])  + fmaf(a2.z, w[10], a2.w * w[11]);
        float d3 = fmaf(a3.x, w[12], a3.y * w[13]) + fmaf(a3.z, w[14], a3.w * w[15]);
        Cv[k] = (d0 + d1) + (d2 + d3);
    }
    float s = Cv[0];
#pragma unroll
    for (int k = 1; k < 16; ++k) s = fmaxf(s, Cv[k]);
    float r = __fdividef(1.0f, s);
    if (lane < 16) {
#pragma unroll
        for (int k = 0; k < 16; ++k) dstM[p * 256 + k * 16 + c] = Cv[k] * r;
        dstLam[p * 16 + c] = lamP + mA + __logf(s);
    }
}

__global__ __launch_bounds__(512, 1) void hmm_combine_tree(
    const float* __restrict__ alogp,
    const float* __restrict__ stopl,
    const float* __restrict__ startl,
    const int* __restrict__ actions,
    const int* __restrict__ lengths,
    float* __restrict__ out)
{
    extern __shared__ __align__(16) float sm[];
    float* bufA = sm;                         // 64*256
    float* bufB = bufA + 64 * 256;            // 32*256
    float* lamA = bufB + 32 * 256;            // 64*16
    float* lamB = lamA + 64 * 16;             // 32*16
    __shared__ __align__(16) float sea[16][16];

    const int b    = blockIdx.x;
    const int warp = threadIdx.x >> 5;
    const int lane = threadIdx.x & 31;

    const float* gM = g_mats + (size_t)b * NC * 256;
    const float* gL = g_lam  + (size_t)b * NC * 16;

    // level 1: 128 -> 64  (gmem -> bufA)
    for (int p = warp; p < 64; p += 16)
        mat_product(gM, gL, bufA, lamA, p, lane, sea[warp]);
    __syncthreads();
    // level 2: 64 -> 32
    for (int p = warp; p < 32; p += 16)
        mat_product(bufA, lamA, bufB, lamB, p, lane, sea[warp]);
    __syncthreads();
    // level 3: 32 -> 16
    if (warp < 16) mat_product(bufB, lamB, bufA, lamA, warp, lane, sea[warp]);
    __syncthreads();
    // level 4: 16 -> 8
    if (warp < 8) mat_product(bufA, lamA, bufB, lamB, warp, lane, sea[warp]);
    __syncthreads();
    // level 5: 8 -> 4
    if (warp < 4) mat_product(bufB, lamB, bufA, lamA, warp, lane, sea[warp]);
    __syncthreads();
    // level 6: 4 -> 2
    if (warp < 2) mat_product(bufA, lamA, bufB, lamB, warp, lane, sea[warp]);
    __syncthreads();
    // level 7: 2 -> 1  (final matrix in bufA[0], lam in lamA[0..15])
    if (warp == 0) mat_product(bufB, lamB, bufA, lamA, 0, lane, sea[0]);
    __syncthreads();

    if (warp == 0) {
        const int c = lane & 15;
        const int len = lengths[b];
        const size_t rb = (size_t)b * T1;
        const int a0i = actions[(size_t)b * MAXT];

        // f0 (step 0)
        float f0 = startl[rb * 16 + c] + alogp[(rb * 16 + (size_t)c) * 18 + a0i];
        float t = lamA[c] + f0;
        float F0 = t;
        F0 = fmaxf(F0, __shfl_xor_sync(0xffffffffu, F0, 1));
        F0 = fmaxf(F0, __shfl_xor_sync(0xffffffffu, F0, 2));
        F0 = fmaxf(F0, __shfl_xor_sync(0xffffffffu, F0, 4));
        F0 = fmaxf(F0, __shfl_xor_sync(0xffffffffu, F0, 8));
        if (lane < 16) sea[0][c] = __expf(t - F0);
        __syncwarp();
        // v_k = (M w)_k, lane k computes row k
        const float4* M4 = (const float4*)bufA;
        const float4* W4 = (const float4*)sea[0];
        float4 m0 = M4[c * 4 + 0], m1 = M4[c * 4 + 1];
        float4 m2 = M4[c * 4 + 2], m3 = M4[c * 4 + 3];
        float4 w0 = W4[0], w1 = W4[1], w2 = W4[2], w3 = W4[3];
        float d0 = fmaf(m0.x, w0.x, m0.y * w0.y) + fmaf(m0.z, w0.z, m0.w * w0.w);
        float d1 = fmaf(m1.x, w1.x, m1.y * w1.y) + fmaf(m1.z, w1.z, m1.w * w1.w);
        float d2 = fmaf(m2.x, w2.x, m2.y * w2.y) + fmaf(m2.z, w2.z, m2.w * w2.w);
        float d3 = fmaf(m3.x, w3.x, m3.y * w3.y) + fmaf(m3.z, w3.z, m3.w * w3.w);
        float v = (d0 + d1) + (d2 + d3);

        // stop at T=len
        float u = stopl[((rb + (size_t)len) * 16 + (size_t)c) * 2];
        float mS = u;
        mS = fmaxf(mS, __shfl_xor_sync(0xffffffffu, mS, 1));
        mS = fmaxf(mS, __shfl_xor_sync(0xffffffffu, mS, 2));
        mS = fmaxf(mS, __shfl_xor_sync(0xffffffffu, mS, 4));
        mS = fmaxf(mS, __shfl_xor_sync(0xffffffffu, mS, 8));
        float term = __expf(u - mS) * v;
        term += __shfl_xor_sync(0xffffffffu, term, 1);
        term += __shfl_xor_sync(0xffffffffu, term, 2);
        term += __shfl_xor_sync(0xffffffffu, term, 4);
        term += __shfl_xor_sync(0xffffffffu, term, 8);
        if (lane == 0) atomicAdd(out, -(F0 + mS + __logf(term)));
    }
}

#define COMBINE_SMEM ((64 * 256 + 32 * 256 + 64 * 16 + 32 * 16) * 4)

extern "C" void kernel_launch(void* const* d_in, const int* in_sizes, int n_in,
                              void* d_out, int out_size)
{
    const float* alogp   = (const float*)d_in[0];
    const float* stopl   = (const float*)d_in[1];
    const float* startl  = (const float*)d_in[2];
    const int*   actions = (const int*)d_in[3];
    const int*   lengths = (const int*)d_in[4];
    float* out = (float*)d_out;

    cudaFuncSetAttribute(hmm_combine_tree,
                         cudaFuncAttributeMaxDynamicSharedMemorySize, COMBINE_SMEM);

    hmm_chunk_kernel<<<(NB * NC / 2) / 4, 128>>>(alogp, stopl, startl, actions, lengths, out);
    hmm_combine_tree<<<NB, 512, COMBINE_SMEM>>>(alogp, stopl, startl, actions, lengths, out);
}

// round 4
// speedup vs baseline: 1.4093x; 1.2618x over previous
#include <cuda_runtime.h>

// Problem constants (fixed by the dataset)
#define NB   64          // batch
#define T1   4097        // maxT+1
#define MAXT 4096
#define HB   16          // hidden states
#define NA   18          // actions
#define CL   64          // chunk length (steps per chunk)
#define NPR  32          // chunk-pairs per batch (each warp folds 2 chunks -> 1 matrix)

// Scratch: per (batch, pair) folded transfer matrix, column c scaled by exp(lam[c]).
__device__ float g_mats[NB * NPR * HB * HB];   // 2 MB
__device__ float g_lam[NB * NPR * HB];

// Prefetch bank: 8 steps of (stop.xy, start, action_logp) per lane.
struct PFB { float2 s[8]; float t[8]; float a[8]; };

__device__ __forceinline__ void load_group(
    int g0, int nact, unsigned idx16_0,
    const float2* __restrict__ stop2, const float* __restrict__ startl,
    const float* __restrict__ alogp, const int* __restrict__ sa,
    PFB& B)
{
#pragma unroll
    for (int u = 0; u < 8; ++u) {
        int t = g0 + u;
        if (t < nact) {
            unsigned idx = idx16_0 + (unsigned)t * 16u;
            B.s[u] = __ldg(stop2 + idx);                         // (beta, omb)
            B.t[u] = __ldg(startl + idx);                        // start
            B.a[u] = __ldg(alogp + idx * 18u + (unsigned)sa[t]); // action logp
        } else {
            B.s[u] = make_float2(0.f, 0.f); B.t[u] = 0.f; B.a[u] = 0.f;
        }
    }
}

// Per step i (exact linear map):
//   s     = sum_j exp(beta_j) * p[j]
//   p[k] <- exp(al_k+start_k)*s + exp(al_k+omb_k)*p[k]
// Every 2 steps: p /= s, lam += log(s)  (conditioning; p*e^lam invariant).
__device__ __forceinline__ void consume_group(
    int g0, int nsteps, int nact, int c, float* __restrict__ vb2,
    PFB& B, float (&p)[HB], float& lam)
{
#pragma unroll
    for (int u = 0; u < 8; ++u) {
        int t = g0 + u;
        if (t >= nsteps) return;   // nsteps is warp-uniform
        float eb   = __expf(B.s[u].x);
        float easv = __expf(B.a[u] + B.t[u]);
        float eaov = __expf(B.a[u] + B.s[u].y);
        float* vb = vb2 + (u & 1) * 48;
        vb[c]      = eb;
        vb[16 + c] = easv;
        vb[32 + c] = eaov;
        __syncwarp();
        const float4* EB = (const float4*)vb;
        float4 e0 = EB[0], e1 = EB[1], e2 = EB[2], e3 = EB[3];
        float t0 = fmaf(e0.x, p[0],  e0.y * p[1])  + fmaf(e0.z, p[2],  e0.w * p[3]);
        float t1 = fmaf(e1.x, p[4],  e1.y * p[5])  + fmaf(e1.z, p[6],  e1.w * p[7]);
        float t2 = fmaf(e2.x, p[8],  e2.y * p[9])  + fmaf(e2.z, p[10], e2.w * p[11]);
        float t3 = fmaf(e3.x, p[12], e3.y * p[13]) + fmaf(e3.z, p[14], e3.w * p[15]);
        float s = (t0 + t1) + (t2 + t3);
        if (t < nact) {            // uniform within each half-warp
            const float4* EA = (const float4*)(vb + 16);
            const float4* EO = (const float4*)(vb + 32);
            float4 a0 = EA[0], a1 = EA[1], a2 = EA[2], a3 = EA[3];
            float4 o0 = EO[0], o1 = EO[1], o2 = EO[2], o3 = EO[3];
            p[0]  = fmaf(o0.x, p[0],  a0.x * s);
            p[1]  = fmaf(o0.y, p[1],  a0.y * s);
            p[2]  = fmaf(o0.z, p[2],  a0.z * s);
            p[3]  = fmaf(o0.w, p[3],  a0.w * s);
            p[4]  = fmaf(o1.x, p[4],  a1.x * s);
            p[5]  = fmaf(o1.y, p[5],  a1.y * s);
            p[6]  = fmaf(o1.z, p[6],  a1.z * s);
            p[7]  = fmaf(o1.w, p[7],  a1.w * s);
            p[8]  = fmaf(o2.x, p[8],  a2.x * s);
            p[9]  = fmaf(o2.y, p[9],  a2.y * s);
            p[10] = fmaf(o2.z, p[10], a2.z * s);
            p[11] = fmaf(o2.w, p[11], a2.w * s);
            p[12] = fmaf(o3.x, p[12], a3.x * s);
            p[13] = fmaf(o3.y, p[13], a3.y * s);
            p[14] = fmaf(o3.z, p[14], a3.z * s);
            p[15] = fmaf(o3.w, p[15], a3.w * s);
            if (t & 1) {
                float r = __fdividef(1.0f, s);
                lam += __logf(s);
#pragma unroll
                for (int k = 0; k < HB; ++k) p[k] *= r;
            }
        }
    }
}

// One warp handles TWO adjacent chunks (lanes 0-15 = earlier, 16-31 = later)
// and folds them into ONE transfer matrix at the end.
__global__ __launch_bounds__(128) void hmm_chunk_kernel(
    const float* __restrict__ alogp,
    const float* __restrict__ stopl,
    const float* __restrict__ startl,
    const int* __restrict__ actions,
    const int* __restrict__ lengths,
    float* __restrict__ out)
{
    if (blockIdx.x == 0 && threadIdx.x == 0) *out = 0.0f;

    const int wib  = threadIdx.x >> 5;
    const int lane = threadIdx.x & 31;
    const int gw   = blockIdx.x * 4 + wib;     // 0..2047
    const int b    = gw >> 5;                  // 64 batches
    const int pr   = gw & 31;                  // 32 chunk-pairs
    const int sub  = lane >> 4;
    const int c    = lane & 15;
    const int ch   = pr * 2 + sub;
    const int i0   = 1 + ch * CL;

    __shared__ int s_act[4][2 * CL];
    __shared__ __align__(16) float s_vec[4][2][2][3 * HB];
    __shared__ __align__(16) float s_m1[4][HB][HB + 1];
    __shared__ float s_lam1[4][HB];

    const int len = lengths[b];

    int cnt  = min(CL, MAXT - i0);
    int nact = max(0, min(len - i0, cnt));
    const int i0p  = 1 + pr * 2 * CL;
    int n0 = max(0, min(len - i0p, min(CL, MAXT - i0p)));
    int n1 = max(0, min(len - (i0p + CL), min(CL, MAXT - (i0p + CL))));
    int nsteps = max(n0, n1);

    int totA = min(2 * CL, MAXT - i0p);
    for (int idx = lane; idx < totA; idx += 32)
        s_act[wib][idx] = actions[(size_t)b * MAXT + i0p + idx];
    __syncwarp();

    float p[HB];
#pragma unroll
    for (int k = 0; k < HB; ++k) p[k] = (k == c) ? 1.0f : 0.0f;
    float lam = 0.0f;

    if (nsteps > 0) {
        const unsigned idx16_0 = ((unsigned)b * T1 + (unsigned)i0) * 16u + (unsigned)c;
        const float2* stop2 = (const float2*)stopl;
        const int* sa = &s_act[wib][sub * CL];
        float* vb2 = &s_vec[wib][sub][0][0];

        PFB B0, B1;
        load_group(0, nact, idx16_0, stop2, startl, alogp, sa, B0);
        for (int g0 = 0; g0 < nsteps; g0 += 16) {
            load_group(g0 + 8, nact, idx16_0, stop2, startl, alogp, sa, B1);
            consume_group(g0, nsteps, nact, c, vb2, B0, p, lam);
            if (g0 + 8 < nsteps) {
                load_group(g0 + 16, nact, idx16_0, stop2, startl, alogp, sa, B0);
                consume_group(g0 + 8, nsteps, nact, c, vb2, B1, p, lam);
            }
        }
    }

    // Fold: R_true = M1_true * M0_true.
    // Column c: R[:,c] = e^{lam0_c} * sum_j M0hat[j][c] e^{lam1_j} M1hat[:,j]
    __syncwarp();
    if (sub == 1) {
#pragma unroll
        for (int k = 0; k < HB; ++k) s_m1[wib][c][k] = p[k];   // row c = column c of M1hat
        s_lam1[wib][c] = lam;
    }
    __syncwarp();
    if (sub == 0) {
        float m1 = s_lam1[wib][0];
#pragma unroll
        for (int j = 1; j < HB; ++j) m1 = fmaxf(m1, s_lam1[wib][j]);
        float R[HB];
#pragma unroll
        for (int k = 0; k < HB; ++k) R[k] = 0.0f;
#pragma unroll
        for (int j = 0; j < HB; ++j) {
            float wj = p[j] * __expf(s_lam1[wib][j] - m1);
            const float* Aj = &s_m1[wib][j][0];
#pragma unroll
            for (int k = 0; k < HB; ++k) R[k] = fmaf(wj, Aj[k], R[k]);
        }
        float s = R[0];
#pragma unroll
        for (int k = 1; k < HB; ++k) s = fmaxf(s, R[k]);
        float r = __fdividef(1.0f, s);
        size_t mb = (size_t)(b * NPR + pr) * (HB * HB);
#pragma unroll
        for (int k = 0; k < HB; ++k)
            g_mats[mb + (size_t)k * HB + c] = R[k] * r;
        g_lam[(size_t)(b * NPR + pr) * HB + c] = lam + m1 + __logf(s);
    }
}

// ---------------------------------------------------------------------------
// Tree combine: one block (8 warps, 256 thr) per batch; one warp per product.
// Halves split the 16 output rows -> spill-free (~40 live regs).
//   C[:,c] = sum_j A[:,j] * (e^{lamA_j - mA} * P[j][c]);  renorm by column max.
// ---------------------------------------------------------------------------
__device__ __forceinline__ void mat_product2(
    const float* __restrict__ srcM, const float* __restrict__ srcLam,
    float* __restrict__ dstM, float* __restrict__ dstLam,
    int pidx, int lane, float* __restrict__ sw /* 16-float per-warp scratch */)
{
    const int c = lane & 15;
    const int h = lane >> 4;                    // rows [8h, 8h+8)
    const float* Pm = srcM + (size_t)(2 * pidx) * 256;
    const float* Am = srcM + (size_t)(2 * pidx + 1) * 256;
    float lamP = srcLam[(2 * pidx) * 16 + c];
    float lamA = srcLam[(2 * pidx + 1) * 16 + c];
    float mA = lamA;
    mA = fmaxf(mA, __shfl_xor_sync(0xffffffffu, mA, 1));
    mA = fmaxf(mA, __shfl_xor_sync(0xffffffffu, mA, 2));
    mA = fmaxf(mA, __shfl_xor_sync(0xffffffffu, mA, 4));
    mA = fmaxf(mA, __shfl_xor_sync(0xffffffffu, mA, 8));
    if (lane < 16) sw[c] = __expf(lamA - mA);
    __syncwarp();
    float w[16];
#pragma unroll
    for (int j = 0; j < 16; ++j) w[j] = sw[j] * Pm[j * 16 + c];
    __syncwarp();
    float Cv[8];
#pragma unroll
    for (int k8 = 0; k8 < 8; ++k8) {
        const float4* A4 = (const float4*)(Am + (h * 8 + k8) * 16);
        float4 a0 = A4[0], a1 = A4[1], a2 = A4[2], a3 = A4[3];
        float d0 = fmaf(a0.x, w[0],  a0.y * w[1])  + fmaf(a0.z, w[2],  a0.w * w[3]);
        float d1 = fmaf(a1.x, w[4],  a1.y * w[5])  + fmaf(a1.z, w[6],  a1.w * w[7]);
        float d2 = fmaf(a2.x, w[8],  a2.y * w[9])  + fmaf(a2.z, w[10], a2.w * w[11]);
        float d3 = fmaf(a3.x, w[12], a3.y * w[13]) + fmaf(a3.z, w[14], a3.w * w[15]);
        Cv[k8] = (d0 + d1) + (d2 + d3);
    }
    float s = Cv[0];
#pragma unroll
    for (int k8 = 1; k8 < 8; ++k8) s = fmaxf(s, Cv[k8]);
    s = fmaxf(s, __shfl_xor_sync(0xffffffffu, s, 16));   // combine halves
    float r = __fdividef(1.0f, s);
#pragma unroll
    for (int k8 = 0; k8 < 8; ++k8)
        dstM[pidx * 256 + (h * 8 + k8) * 16 + c] = Cv[k8] * r;
    if (lane < 16) dstLam[pidx * 16 + c] = lamP + mA + __logf(s);
}

__global__ __launch_bounds__(256, 1) void hmm_combine_tree(
    const float* __restrict__ alogp,
    const float* __restrict__ stopl,
    const float* __restrict__ startl,
    const int* __restrict__ actions,
    const int* __restrict__ lengths,
    float* __restrict__ out)
{
    __shared__ __align__(16) float bufA[16 * 256];
    __shared__ __align__(16) float bufB[8 * 256];
    __shared__ float lamA[16 * 16];
    __shared__ float lamB[8 * 16];
    __shared__ __align__(16) float sw[8][16];

    const int b    = blockIdx.x;
    const int warp = threadIdx.x >> 5;
    const int lane = threadIdx.x & 31;

    const float* gM = g_mats + (size_t)b * NPR * 256;
    const float* gL = g_lam  + (size_t)b * NPR * 16;

    // L1: 32 -> 16 (gmem -> bufA); each warp does 2 products
    mat_product2(gM, gL, bufA, lamA, warp,     lane, sw[warp]);
    mat_product2(gM, gL, bufA, lamA, warp + 8, lane, sw[warp]);
    __syncthreads();
    // L2: 16 -> 8
    mat_product2(bufA, lamA, bufB, lamB, warp, lane, sw[warp]);
    __syncthreads();
    // L3: 8 -> 4
    if (warp < 4) mat_product2(bufB, lamB, bufA, lamA, warp, lane, sw[warp]);
    __syncthreads();
    // L4: 4 -> 2
    if (warp < 2) mat_product2(bufA, lamA, bufB, lamB, warp, lane, sw[warp]);
    __syncthreads();
    // L5: 2 -> 1  (final in bufA[0], lam in lamA[0..15])
    if (warp == 0) mat_product2(bufB, lamB, bufA, lamA, 0, lane, sw[0]);
    __syncthreads();

    if (warp == 0) {
        const int c = lane & 15;
        const int len = lengths[b];
        const size_t rb = (size_t)b * T1;
        const int a0i = actions[(size_t)b * MAXT];

        float f0 = startl[rb * 16 + c] + alogp[(rb * 16 + (size_t)c) * 18 + a0i];
        float t = lamA[c] + f0;
        float F0 = t;
        F0 = fmaxf(F0, __shfl_xor_sync(0xffffffffu, F0, 1));
        F0 = fmaxf(F0, __shfl_xor_sync(0xffffffffu, F0, 2));
        F0 = fmaxf(F0, __shfl_xor_sync(0xffffffffu, F0, 4));
        F0 = fmaxf(F0, __shfl_xor_sync(0xffffffffu, F0, 8));
        if (lane < 16) sw[0][c] = __expf(t - F0);
        __syncwarp();
        const float4* M4 = (const float4*)bufA;
        const float4* W4 = (const float4*)sw[0];
        float4 m0 = M4[c * 4 + 0], m1 = M4[c * 4 + 1];
        float4 m2 = M4[c * 4 + 2], m3 = M4[c * 4 + 3];
        float4 w0 = W4[0], w1 = W4[1], w2 = W4[2], w3 = W4[3];
        float d0 = fmaf(m0.x, w0.x, m0.y * w0.y) + fmaf(m0.z, w0.z, m0.w * w0.w);
        float d1 = fmaf(m1.x, w1.x, m1.y * w1.y) + fmaf(m1.z, w1.z, m1.w * w1.w);
        float d2 = fmaf(m2.x, w2.x, m2.y * w2.y) + fmaf(m2.z, w2.z, m2.w * w2.w);
        float d3 = fmaf(m3.x, w3.x, m3.y * w3.y) + fmaf(m3.z, w3.z, m3.w * w3.w);
        float v = (d0 + d1) + (d2 + d3);      // lane c: (M w)_c

        float u = stopl[((rb + (size_t)len) * 16 + (size_t)c) * 2];
        float mS = u;
        mS = fmaxf(mS, __shfl_xor_sync(0xffffffffu, mS, 1));
        mS = fmaxf(mS, __shfl_xor_sync(0xffffffffu, mS, 2));
        mS = fmaxf(mS, __shfl_xor_sync(0xffffffffu, mS, 4));
        mS = fmaxf(mS, __shfl_xor_sync(0xffffffffu, mS, 8));
        float term = __expf(u - mS) * v;
        term += __shfl_xor_sync(0xffffffffu, term, 1);
        term += __shfl_xor_sync(0xffffffffu, term, 2);
        term += __shfl_xor_sync(0xffffffffu, term, 4);
        term += __shfl_xor_sync(0xffffffffu, term, 8);
        if (lane == 0) atomicAdd(out, -(F0 + mS + __logf(term)));
    }
}

extern "C" void kernel_launch(void* const* d_in, const int* in_sizes, int n_in,
                              void* d_out, int out_size)
{
    const float* alogp   = (const float*)d_in[0];
    const float* stopl   = (const float*)d_in[1];
    const float* startl  = (const float*)d_in[2];
    const int*   actions = (const int*)d_in[3];
    const int*   lengths = (const int*)d_in[4];
    float* out = (float*)d_out;

    hmm_chunk_kernel<<<(NB * NPR) / 4, 128>>>(alogp, stopl, startl, actions, lengths, out);
    hmm_combine_tree<<<NB, 256>>>(alogp, stopl, startl, actions, lengths, out);
}